// round 17
// baseline (speedup 1.0000x reference)
#include <cuda_runtime.h>
#include <cuda_bf16.h>
#include <cuda_fp16.h>
#include <cstdint>

static constexpr int B_ = 128, P_ = 196, ENC_ = 2048, A_ = 512, H_ = 512;
static constexpr int V_ = 20000, T_ = 20, H3_ = 1536, EX_ = 2560;
static constexpr long CAP_OFF   = (long)B_ * T_ * V_;   // 51,200,000
static constexpr long ALPHA_OFF = CAP_OFF + B_;         // 51,200,128
static constexpr int  M1_ = B_ * P_;                    // 25088
static constexpr int  MH_ = (T_ - 1) * B_;              // 2432

// ---------------- device scratch ------------------------------------------
__device__ __align__(16) __half g_img16[(size_t)M1_ * ENC_];
__device__ __align__(16) __half g_att1h[(size_t)M1_ * A_];
__device__ __align__(16) __half g_WeT16[A_ * ENC_];
__device__ __align__(16) __half g_WdT16[A_ * H_];
__device__ __align__(16) __half g_Whh16[H3_ * H_];
__device__ __align__(16) __half g_Wih16[H3_ * EX_];
__device__ __align__(16) __half g_Wo16[(size_t)V_ * H_];
__device__ __align__(16) __half g_Xemb16[MH_ * 512];
__device__ __align__(16) float  g_gi_emb[(size_t)MH_ * H3_];
__device__ __align__(16) float  g_gh2[2][B_ * H3_];     // split-K partials: gh
__device__ __align__(16) float  g_gi4[4][B_ * H3_];     // split-K partials: gi_ctx
__device__ __align__(16) float  g_alpha[B_ * P_];
__device__ __align__(16) __half g_x16[B_ * ENC_];       // ctx fp16
__device__ __align__(16) float  g_h[B_ * H_];
__device__ __align__(16) __half g_h16[B_ * H_];
__device__ __align__(16) __half g_hall16[MH_ * H_];

// ---------------- helpers --------------------------------------------------
__device__ __forceinline__ uint32_t s2u(const void* p) {
    return (uint32_t)__cvta_generic_to_shared(p);
}
__device__ __forceinline__ void ldsm4(uint32_t r[4], uint32_t a) {
    asm volatile("ldmatrix.sync.aligned.m8n8.x4.shared.b16 {%0,%1,%2,%3},[%4];"
                 : "=r"(r[0]), "=r"(r[1]), "=r"(r[2]), "=r"(r[3]) : "r"(a));
}
__device__ __forceinline__ void mma16816h(float c[4], const uint32_t a[4], const uint32_t b[2]) {
    asm volatile(
        "mma.sync.aligned.m16n8k16.row.col.f32.f16.f16.f32 "
        "{%0,%1,%2,%3},{%4,%5,%6,%7},{%8,%9},{%0,%1,%2,%3};"
        : "+f"(c[0]), "+f"(c[1]), "+f"(c[2]), "+f"(c[3])
        : "r"(a[0]), "r"(a[1]), "r"(a[2]), "r"(a[3]), "r"(b[0]), "r"(b[1]));
}
#define CP16(d, s) asm volatile("cp.async.cg.shared.global [%0],[%1],16;\n" :: "r"(d), "l"(s))
#define CPCOMMIT() asm volatile("cp.async.commit_group;\n")

// ---------------- fp16 1-MMA GEMM infrastructure ----------------------------
static constexpr int S1A = 128 * 40;
static constexpr int S1B = 64 * 40;
static constexpr int S1TG = S1A + S1B;             // 7680 halves
static constexpr int GEMM1_SMEM = 2 * S1TG * 2;    // 30720 B

// device tile worker: C[0..127, n0..n0+63] (+=K slice), M=128 fixed, m0=0.
__device__ __forceinline__ void gemm_tile(
    const __half* __restrict__ Ag, int lda,
    const __half* __restrict__ Bg, int ldb,
    const float* __restrict__ bias, float* __restrict__ C, long row_stride,
    int n0, int kbase, int Ksub, __half* smh)
{
    const int tid = threadIdx.x, lane = tid & 31, warp = tid >> 5;
    const int wm = warp >> 1, wn = warp & 1;

    float acc[2][4][4];
#pragma unroll
    for (int i = 0; i < 2; i++)
#pragma unroll
        for (int j = 0; j < 4; j++)
#pragma unroll
            for (int k = 0; k < 4; k++) acc[i][j][k] = 0.f;

    auto load_stage = [&](int st, int k0) {
        __half* As = smh + st * S1TG;
        __half* Bs = As + S1A;
#pragma unroll
        for (int it = 0; it < 2; it++) {
            int idx = tid + it * 256, r = idx >> 2, ch = idx & 3;
            CP16(s2u(As + r * 40 + ch * 8), Ag + (size_t)r * lda + kbase + k0 + ch * 8);
        }
        {
            int r = tid >> 2, ch = tid & 3;
            CP16(s2u(Bs + r * 40 + ch * 8), Bg + (size_t)(n0 + r) * ldb + kbase + k0 + ch * 8);
        }
        CPCOMMIT();
    };

    const int nk = Ksub / 32;
    load_stage(0, 0);
    for (int i = 0; i < nk; i++) {
        if (i + 1 < nk) {
            load_stage((i + 1) & 1, (i + 1) * 32);
            asm volatile("cp.async.wait_group 1;\n");
        } else {
            asm volatile("cp.async.wait_group 0;\n");
        }
        __syncthreads();
        __half* As = smh + (i & 1) * S1TG;
        __half* Bs = As + S1A;
#pragma unroll
        for (int kk = 0; kk < 32; kk += 16) {
            uint32_t ah[2][4], bh[4][2];
#pragma unroll
            for (int mt = 0; mt < 2; mt++) {
                int off = (wm * 32 + mt * 16 + (lane & 15)) * 40 + kk + ((lane >> 4) << 3);
                ldsm4(ah[mt], s2u(As + off));
            }
#pragma unroll
            for (int ng = 0; ng < 2; ng++) {
                int off = (wn * 32 + ng * 16 + (lane & 15)) * 40 + kk + ((lane >> 4) << 3);
                uint32_t t4[4];
                ldsm4(t4, s2u(Bs + off));
                bh[ng * 2][0] = t4[0]; bh[ng * 2][1] = t4[2];
                bh[ng * 2 + 1][0] = t4[1]; bh[ng * 2 + 1][1] = t4[3];
            }
#pragma unroll
            for (int mt = 0; mt < 2; mt++)
#pragma unroll
                for (int nt = 0; nt < 4; nt++)
                    mma16816h(acc[mt][nt], ah[mt], bh[nt]);
        }
        __syncthreads();
    }

    const bool addb = (bias != nullptr);
#pragma unroll
    for (int mt = 0; mt < 2; mt++) {
        int r = wm * 32 + mt * 16 + (lane >> 2);
#pragma unroll
        for (int nt = 0; nt < 4; nt++) {
            int col = n0 + wn * 32 + nt * 8 + (lane & 3) * 2;
            float b0 = addb ? bias[col] : 0.f;
            float b1 = addb ? bias[col + 1] : 0.f;
            C[(long)r * row_stride + col]           = acc[mt][nt][0] + b0;
            C[(long)(r + 8) * row_stride + col]     = acc[mt][nt][2] + b0;
            C[(long)r * row_stride + col + 1]       = acc[mt][nt][1] + b1;
            C[(long)(r + 8) * row_stride + col + 1] = acc[mt][nt][3] + b1;
        }
    }
}

// host-callable GEMM (fixed parts)
__global__ __launch_bounds__(256) void gemm1h(
    const __half* __restrict__ Ag, int lda,
    const __half* __restrict__ Bg, int ldb,
    const float* __restrict__ bias, void* __restrict__ Cbase,
    long tile_stride, long row_stride,
    int N, int Ktot, int out_half)
{
    extern __shared__ __align__(16) __half smh[];
    const int tid = threadIdx.x, lane = tid & 31, warp = tid >> 5;
    const int wm = warp >> 1, wn = warp & 1;
    const int n0 = blockIdx.x * 64, m0 = blockIdx.y * 128;

    float acc[2][4][4];
#pragma unroll
    for (int i = 0; i < 2; i++)
#pragma unroll
        for (int j = 0; j < 4; j++)
#pragma unroll
            for (int k = 0; k < 4; k++) acc[i][j][k] = 0.f;

    auto load_stage = [&](int st, int k0) {
        __half* As = smh + st * S1TG;
        __half* Bs = As + S1A;
#pragma unroll
        for (int it = 0; it < 2; it++) {
            int idx = tid + it * 256, r = idx >> 2, ch = idx & 3;
            CP16(s2u(As + r * 40 + ch * 8), Ag + (size_t)(m0 + r) * lda + k0 + ch * 8);
        }
        {
            int r = tid >> 2, ch = tid & 3;
            int rr = (n0 + r < N) ? (n0 + r) : (N - 1);
            CP16(s2u(Bs + r * 40 + ch * 8), Bg + (size_t)rr * ldb + k0 + ch * 8);
        }
        CPCOMMIT();
    };

    const int nk = Ktot / 32;
    load_stage(0, 0);
    for (int i = 0; i < nk; i++) {
        if (i + 1 < nk) {
            load_stage((i + 1) & 1, (i + 1) * 32);
            asm volatile("cp.async.wait_group 1;\n");
        } else {
            asm volatile("cp.async.wait_group 0;\n");
        }
        __syncthreads();
        __half* As = smh + (i & 1) * S1TG;
        __half* Bs = As + S1A;
#pragma unroll
        for (int kk = 0; kk < 32; kk += 16) {
            uint32_t ah[2][4], bh[4][2];
#pragma unroll
            for (int mt = 0; mt < 2; mt++) {
                int off = (wm * 32 + mt * 16 + (lane & 15)) * 40 + kk + ((lane >> 4) << 3);
                ldsm4(ah[mt], s2u(As + off));
            }
#pragma unroll
            for (int ng = 0; ng < 2; ng++) {
                int off = (wn * 32 + ng * 16 + (lane & 15)) * 40 + kk + ((lane >> 4) << 3);
                uint32_t t4[4];
                ldsm4(t4, s2u(Bs + off));
                bh[ng * 2][0] = t4[0]; bh[ng * 2][1] = t4[2];
                bh[ng * 2 + 1][0] = t4[1]; bh[ng * 2 + 1][1] = t4[3];
            }
#pragma unroll
            for (int mt = 0; mt < 2; mt++)
#pragma unroll
                for (int nt = 0; nt < 4; nt++)
                    mma16816h(acc[mt][nt], ah[mt], bh[nt]);
        }
        __syncthreads();
    }

    const bool addb = (bias != nullptr);
    if (!out_half) {
        float* Cp = (float*)Cbase + (long)blockIdx.y * tile_stride;
#pragma unroll
        for (int mt = 0; mt < 2; mt++) {
            int r = wm * 32 + mt * 16 + (lane >> 2);
#pragma unroll
            for (int nt = 0; nt < 4; nt++) {
                int col = n0 + wn * 32 + nt * 8 + (lane & 3) * 2;
                if (col < N) {
                    float bb = addb ? bias[col] : 0.f;
                    Cp[(long)r * row_stride + col]       = acc[mt][nt][0] + bb;
                    Cp[(long)(r + 8) * row_stride + col] = acc[mt][nt][2] + bb;
                }
                if (col + 1 < N) {
                    float bb = addb ? bias[col + 1] : 0.f;
                    Cp[(long)r * row_stride + col + 1]       = acc[mt][nt][1] + bb;
                    Cp[(long)(r + 8) * row_stride + col + 1] = acc[mt][nt][3] + bb;
                }
            }
        }
    } else {
        __half* Cp = (__half*)Cbase + (long)blockIdx.y * tile_stride;
#pragma unroll
        for (int mt = 0; mt < 2; mt++) {
            int r = wm * 32 + mt * 16 + (lane >> 2);
#pragma unroll
            for (int nt = 0; nt < 4; nt++) {
                int col = n0 + wn * 32 + nt * 8 + (lane & 3) * 2;
                float b0 = addb ? bias[col] : 0.f;
                float b1 = addb ? bias[col + 1] : 0.f;
                __half2 w0 = {__float2half_rn(acc[mt][nt][0] + b0), __float2half_rn(acc[mt][nt][1] + b1)};
                __half2 w1 = {__float2half_rn(acc[mt][nt][2] + b0), __float2half_rn(acc[mt][nt][3] + b1)};
                *(__half2*)(Cp + (long)r * row_stride + col)       = w0;
                *(__half2*)(Cp + (long)(r + 8) * row_stride + col) = w1;
            }
        }
    }
}

// ---------------- dual per-step GEMM: gh (48 blk) + gi_ctx (96 blk) ---------
__global__ __launch_bounds__(256) void dual_k(const float* __restrict__ bhh)
{
    extern __shared__ __align__(16) __half smh[];
    const int bid = blockIdx.x;
    if (bid < 48) {
        // gh = h16 @ Whh^T (+bhh on ks0), split-K=2 over K=512
        int ks = bid & 1, nt = bid >> 1;
        gemm_tile(g_h16, 512, g_Whh16, 512, (ks == 0) ? bhh : nullptr,
                  g_gh2[ks], 1536, nt * 64, ks * 256, 256, smh);
    } else {
        // gi_ctx = x16 @ Wih[:, 512:]^T, split-K=4 over K=2048
        int b2 = bid - 48, ks = b2 & 3, nt = b2 >> 2;
        gemm_tile(g_x16, 2048, g_Wih16 + 512, 2560, nullptr,
                  g_gi4[ks], 1536, nt * 64, ks * 512, 512, smh);
    }
}

// ---------------- prep kernels ----------------------------------------------
__global__ void prep_img_k(const float* __restrict__ src, long n4)
{
    long i = (long)blockIdx.x * 256 + threadIdx.x;
    if (i >= n4) return;
    float4 v = ((const float4*)src)[i];
    ((__half2*)(g_img16 + 4 * i))[0] = {__float2half_rn(v.x), __float2half_rn(v.y)};
    ((__half2*)(g_img16 + 4 * i))[1] = {__float2half_rn(v.z), __float2half_rn(v.w)};
}

__global__ void tofp16_k(const float* __restrict__ src, __half* __restrict__ d, long n4)
{
    long i = (long)blockIdx.x * 256 + threadIdx.x;
    if (i >= n4) return;
    float4 v = ((const float4*)src)[i];
    ((__half2*)(d + 4 * i))[0] = {__float2half_rn(v.x), __float2half_rn(v.y)};
    ((__half2*)(d + 4 * i))[1] = {__float2half_rn(v.z), __float2half_rn(v.w)};
}

__global__ void transpose_h(const float* __restrict__ src, __half* __restrict__ d,
                            int R, int C)
{
    __shared__ float tile[32][33];
    int c0 = blockIdx.x * 32, r0 = blockIdx.y * 32;
    int tx = threadIdx.x, ty = threadIdx.y;  // (32, 8)
#pragma unroll
    for (int i = 0; i < 4; i++) {
        int r = r0 + ty + i * 8;
        if (r < R && c0 + tx < C) tile[ty + i * 8][tx] = src[(size_t)r * C + c0 + tx];
    }
    __syncthreads();
#pragma unroll
    for (int i = 0; i < 4; i++) {
        int orow = c0 + ty + i * 8, ocol = r0 + tx;
        if (orow < C && ocol < R)
            d[(size_t)orow * R + ocol] = __float2half_rn(tile[tx][ty + i * 8]);
    }
}

__global__ void emb_gather_k(const float* __restrict__ emb, const int* __restrict__ cap)
{
    const int b = blockIdx.x, tt = blockIdx.y;   // tt = t-1, 0..18
    const int w = cap[b * 20 + tt];
    __half* dst = g_Xemb16 + (size_t)(tt * 128 + b) * 512;
    const float* s = emb + (size_t)w * 512;
    for (int i = threadIdx.x; i < 512; i += 128) dst[i] = __float2half_rn(s[i]);
}

__global__ void zero_h_k()
{
    int i = blockIdx.x * 256 + threadIdx.x;
    if (i < B_ * H_) { g_h[i] = 0.f; g_h16[i] = __float2half_rn(0.f); }
}

__global__ void init_out_k(float* __restrict__ out, const int* __restrict__ caplen)
{
    long i = (long)blockIdx.x * 256 + threadIdx.x;
    const long n0 = (long)B_ * V_;
    if (i < n0) {
        long b = i / V_, v2 = i % V_;
        out[b * 400000 + v2] = (v2 == 1) ? 1.f : 0.f;
    } else if (i < n0 + B_ * P_) {
        long j = i - n0, b = j / P_, p = j % P_;
        out[ALPHA_OFF + b * (T_ * P_) + p] = 0.f;
    } else if (i < n0 + B_ * P_ + B_) {
        int b = (int)(i - n0 - B_ * P_);
        out[CAP_OFF + b] = (float)caplen[b];
    }
}

// ---------------- per-step kernels ------------------------------------------
// score_softmax with in-block att2 = h16[b] @ WdT^T + bd  (FFMA, Wd L1/L2-hot)
__global__ __launch_bounds__(256) void score_softmax_k(
    const float* __restrict__ bd, const float* __restrict__ wf,
    const float* __restrict__ bfp, float* __restrict__ out, int t)
{
    __shared__ float hs[512], att2s[512], wfs[512], sc[200], red[256];
    const int b = blockIdx.x, tid = threadIdx.x, lane = tid & 31, warp = tid >> 5;
    // load h16[b] -> smem floats; wf -> smem
    for (int i = tid; i < 256; i += 256) {
        float2 hv = __half22float2(((const __half2*)(g_h16 + b * 512))[i]);
        hs[2 * i] = hv.x; hs[2 * i + 1] = hv.y;
    }
    for (int i = tid; i < 512; i += 256) wfs[i] = wf[i];
    __syncthreads();
    // att2
    for (int jj = tid; jj < 512; jj += 256) {
        const __half2* wr = (const __half2*)(g_WdT16 + (size_t)jj * 512);
        float s = 0.f;
#pragma unroll 8
        for (int k2 = 0; k2 < 256; k2++) {
            float2 w = __half22float2(wr[k2]);
            s += w.x * hs[2 * k2] + w.y * hs[2 * k2 + 1];
        }
        att2s[jj] = s + bd[jj];
    }
    __syncthreads();
    const float bfv = bfp[0];
    for (int p = warp; p < 196; p += 8) {
        const __half2* row = (const __half2*)(g_att1h + ((size_t)b * 196 + p) * 512);
        float s = 0.f;
#pragma unroll
        for (int i = 0; i < 8; i++) {
            int c = lane + i * 32;
            float2 vf = __half22float2(row[c]);
            s += fmaxf(vf.x + att2s[2 * c], 0.f) * wfs[2 * c]
               + fmaxf(vf.y + att2s[2 * c + 1], 0.f) * wfs[2 * c + 1];
        }
#pragma unroll
        for (int o = 16; o; o >>= 1) s += __shfl_xor_sync(0xffffffffu, s, o);
        if (lane == 0) sc[p] = s + bfv;
    }
    __syncthreads();
    float v = (tid < 196) ? sc[tid] : -1e30f;
    red[tid] = v; __syncthreads();
    for (int o = 128; o; o >>= 1) { if (tid < o) red[tid] = fmaxf(red[tid], red[tid + o]); __syncthreads(); }
    float m = red[0]; __syncthreads();
    float e = (tid < 196) ? __expf(sc[tid] - m) : 0.f;
    red[tid] = e; __syncthreads();
    for (int o = 128; o; o >>= 1) { if (tid < o) red[tid] += red[tid + o]; __syncthreads(); }
    float inv = 1.f / red[0];
    if (tid < 196) {
        float a = e * inv;
        g_alpha[b * 196 + tid] = a;
        out[ALPHA_OFF + ((size_t)b * 20 + t) * 196 + tid] = a;
    }
}

// ctx weighted sum (fp16 img, wide grid) -> x16 [128, 2048] fp16
__global__ void ctx_k()
{
    __shared__ float al[196];
    const int b = blockIdx.y, tid = threadIdx.x;
    for (int i = tid; i < 196; i += 128) al[i] = g_alpha[b * 196 + i];
    __syncthreads();
    const __half2* ip = (const __half2*)(g_img16 + (size_t)b * 196 * 2048);
    const int c0 = blockIdx.x * 256 + tid;   // half2 column, plus c0+128
    float2 a0 = {0.f, 0.f}, a1 = {0.f, 0.f};
#pragma unroll 4
    for (int p = 0; p < 196; p++) {
        const __half2* rp = ip + (size_t)p * 1024;
        float a = al[p];
        float2 v0 = __half22float2(rp[c0]);
        float2 v1 = __half22float2(rp[c0 + 128]);
        a0.x += a * v0.x; a0.y += a * v0.y;
        a1.x += a * v1.x; a1.y += a * v1.y;
    }
    *(__half2*)(g_x16 + b * 2048 + 2 * c0) =
        {__float2half_rn(a0.x), __float2half_rn(a0.y)};
    *(__half2*)(g_x16 + b * 2048 + 2 * (c0 + 128)) =
        {__float2half_rn(a1.x), __float2half_rn(a1.y)};
}

__global__ void gates_k(int t)
{
    int idx = blockIdx.x * 256 + threadIdx.x;
    if (idx >= B_ * H_) return;
    int b = idx >> 9, j = idx & 511;
    const float* ge = g_gi_emb + (size_t)((t - 1) * 128 + b) * 1536;
    int base = b * 1536;
    float gir = ge[j], giz = ge[512 + j], gin = ge[1024 + j];
#pragma unroll
    for (int s = 0; s < 4; s++) {
        gir += g_gi4[s][base + j];
        giz += g_gi4[s][base + 512 + j];
        gin += g_gi4[s][base + 1024 + j];
    }
    float ghr = g_gh2[0][base + j]        + g_gh2[1][base + j];
    float ghz = g_gh2[0][base + 512 + j]  + g_gh2[1][base + 512 + j];
    float ghn = g_gh2[0][base + 1024 + j] + g_gh2[1][base + 1024 + j];
    float r = 1.f / (1.f + __expf(-(gir + ghr)));
    float z = 1.f / (1.f + __expf(-(giz + ghz)));
    float n = tanhf(gin + r * ghn);
    float h = g_h[idx];
    float hn = (1.f - z) * n + z * h;
    g_h[idx] = hn;
    __half h16 = __float2half_rn(hn);
    g_h16[idx] = h16;
    g_hall16[(t - 1) * (B_ * H_) + idx] = h16;
}

// ---------------- host -------------------------------------------------------
extern "C" void kernel_launch(void* const* d_in, const int* in_sizes, int n_in,
                              void* d_out, int out_size)
{
    const float* img = (const float*)d_in[0];
    const int*   cap = (const int*)d_in[1];
    const int*   cpl = (const int*)d_in[2];
    const float* emb = (const float*)d_in[3];
    const float* We  = (const float*)d_in[4];
    const float* be  = (const float*)d_in[5];
    const float* Wd  = (const float*)d_in[6];
    const float* bd  = (const float*)d_in[7];
    const float* Wf  = (const float*)d_in[8];
    const float* bfp = (const float*)d_in[9];
    const float* Wih = (const float*)d_in[10];
    const float* bih = (const float*)d_in[11];
    const float* Whh = (const float*)d_in[12];
    const float* bhh = (const float*)d_in[13];
    const float* Wo  = (const float*)d_in[14];
    const float* bo  = (const float*)d_in[15];
    float* out = (float*)d_out;

    static bool inited = false;
    if (!inited) {
        cudaFuncSetAttribute(gemm1h, cudaFuncAttributeMaxDynamicSharedMemorySize, GEMM1_SMEM);
        cudaFuncSetAttribute(dual_k, cudaFuncAttributeMaxDynamicSharedMemorySize, GEMM1_SMEM);
        inited = true;
    }

    void *pImg16, *pAtt1h, *pWe16, *pWih16, *pWo16, *pXe16, *pGiE, *pHa16;
    cudaGetSymbolAddress(&pImg16, g_img16);
    cudaGetSymbolAddress(&pAtt1h, g_att1h);
    cudaGetSymbolAddress(&pWe16, g_WeT16);
    cudaGetSymbolAddress(&pWih16, g_Wih16);
    cudaGetSymbolAddress(&pWo16, g_Wo16);
    cudaGetSymbolAddress(&pXe16, g_Xemb16);
    cudaGetSymbolAddress(&pGiE, g_gi_emb);
    cudaGetSymbolAddress(&pHa16, g_hall16);
    void *pWdT16, *pWhh16;
    cudaGetSymbolAddress(&pWdT16, g_WdT16);
    cudaGetSymbolAddress(&pWhh16, g_Whh16);

    // ---- prep ----
    {
        long n4 = (long)M1_ * ENC_ / 4;
        prep_img_k<<<(int)((n4 + 255) / 256), 256>>>(img, n4);
    }
    transpose_h<<<dim3(16, 64), dim3(32, 8)>>>(We, (__half*)pWe16, 2048, 512);
    transpose_h<<<dim3(16, 16), dim3(32, 8)>>>(Wd, (__half*)pWdT16, 512, 512);
    {
        long n4 = (long)H3_ * H_ / 4;
        tofp16_k<<<(int)((n4 + 255) / 256), 256>>>(Whh, (__half*)pWhh16, n4);
    }
    {
        long n4 = (long)H3_ * EX_ / 4;
        tofp16_k<<<(int)((n4 + 255) / 256), 256>>>(Wih, (__half*)pWih16, n4);
    }
    {
        long n4 = (long)V_ * H_ / 4;
        tofp16_k<<<(int)((n4 + 255) / 256), 256>>>(Wo, (__half*)pWo16, n4);
    }
    emb_gather_k<<<dim3(128, 19), 128>>>(emb, cap);
    zero_h_k<<<256, 256>>>();
    {
        long tot = (long)B_ * V_ + B_ * P_ + B_;
        init_out_k<<<(int)((tot + 255) / 256), 256>>>(out, cpl);
    }

    // att1 = img16 @ WeT16^T + be -> fp16 [25088, 512]
    gemm1h<<<dim3(8, 196), 256, GEMM1_SMEM>>>(
        (const __half*)pImg16, 2048, (const __half*)pWe16, 2048,
        be, pAtt1h, (long)128 * 512, 512, 512, 2048, 1);

    // gi_emb = Xemb @ Wih[:, :512]^T + bih -> [2432, 1536] fp32
    gemm1h<<<dim3(24, 19), 256, GEMM1_SMEM>>>(
        (const __half*)pXe16, 512, (const __half*)pWih16, 2560,
        bih, pGiE, (long)128 * 1536, 1536, 1536, 512, 0);

    // per-step loop: 4 launches/step
    for (int t = 1; t < 20; t++) {
        score_softmax_k<<<128, 256>>>(bd, Wf, bfp, out, t);
        ctx_k<<<dim3(4, 128), 128>>>();
        dual_k<<<144, 256, GEMM1_SMEM>>>(bhh);
        gates_k<<<256, 256>>>(t);
    }

    // preds (batched): [2432, 20000] -> out[b*400000 + t*20000 + v]
    gemm1h<<<dim3(313, 19), 256, GEMM1_SMEM>>>(
        (const __half*)pHa16, 512, (const __half*)pWo16, 512,
        bo, out + 20000, 20000, 400000, 20000, 512, 0);

    (void)in_sizes; (void)n_in; (void)out_size;
}